// round 12
// baseline (speedup 1.0000x reference)
#include <cuda_runtime.h>
#include <cuda_bf16.h>
#include <cstdint>

// ============================================================================
// ShotHead (GB300 / sm_100a) — round 12: resubmit of round-11 (infra flake).
//   gate  = relu(x @ Wg1 + bg1) @ Wg2 + bg2
//   alpha = e^g / seg_sum(e^g)          (shift-invariant softmax, single pass)
//   hg    = segment_sum(alpha * x)
//   out   = relu(hg @ Wm1 + bm1) @ Wm2 + bm2
//
// vs round 10 (80.9us): head kernel was 13.1us (issue 11%) — 512 short blocks
// serializing stage->sync->one-warp-job. Now 128 blocks, 4 segments per warp,
// hg broadcast via shfl (no shared staging/sync inside the segment loop).
// Chunk kernel unchanged.
// ============================================================================

#define TILE     128
#define NT       256
#define XPITCH   68          // floats per x row in SMEM (17 float4, pad)
#define MAXB     8192

__device__ float g_num[MAXB * 64];
__device__ float g_den[MAXB];

// ---------------- helpers ---------------------------------------------------
__device__ __forceinline__ uint32_t smem_u32(const void* p) {
    uint32_t a;
    asm("{ .reg .u64 t; cvta.to.shared.u64 t, %1; cvt.u32.u64 %0, t; }"
        : "=r"(a) : "l"(p));
    return a;
}
__device__ __forceinline__ void cp_async16(uint32_t dst, const void* src) {
    asm volatile("cp.async.cg.shared.global [%0], [%1], 16;"
                 :: "r"(dst), "l"(src) : "memory");
}
__device__ __forceinline__ void cp_async_wait_all() {
    asm volatile("cp.async.commit_group;\n\tcp.async.wait_group 0;" ::: "memory");
}
__device__ __forceinline__ uint32_t bf16x2_pack(float hi_elem, float lo_elem) {
    uint32_t r;   // low 16 = lo_elem, high 16 = hi_elem
    asm("cvt.rn.bf16x2.f32 %0, %1, %2;" : "=r"(r) : "f"(hi_elem), "f"(lo_elem));
    return r;
}
__device__ __forceinline__ void mma_bf16(float* c, uint32_t a0, uint32_t a1,
                                         uint32_t a2, uint32_t a3,
                                         uint32_t b0, uint32_t b1) {
    asm volatile(
        "mma.sync.aligned.m16n8k16.row.col.f32.bf16.bf16.f32 "
        "{%0,%1,%2,%3}, {%4,%5,%6,%7}, {%8,%9}, {%0,%1,%2,%3};"
        : "+f"(c[0]), "+f"(c[1]), "+f"(c[2]), "+f"(c[3])
        : "r"(a0), "r"(a1), "r"(a2), "r"(a3), "r"(b0), "r"(b1));
}

// ---------------------------------------------------------------------------
// SMEM layout (bytes). W pitch = 72 bf16 = 144 B.
// ---------------------------------------------------------------------------
#define X_OFF    0                          /* 128 x 272B fp32               */
#define WH_OFF   34816                      /* Whi[n][k] 32 x 144B           */
#define WL_OFF   39424                      /* Wlo[n][k] 32 x 144B           */
#define E_OFF    44032                      /* float[128] e                  */
#define BT_OFF   44544                      /* int[128] segment ids          */
#define SB1_OFF  45056                      /* float[32] bg1                 */
#define SW2_OFF  45184                      /* float[32] Wg2                 */
#define SMEM_BYTES 45312

// ---------------------------------------------------------------------------
// Kernel 1: per-chunk gate + e + segmented partial sums. Grid = ceil(N/128).
// ---------------------------------------------------------------------------
__global__ void __launch_bounds__(NT, 4) shothead_chunk(
    const float* __restrict__ x, const void* __restrict__ batch,
    const float* __restrict__ Wg1, const float* __restrict__ bg1,
    const float* __restrict__ Wg2, const float* __restrict__ bg2,
    int N, int B)
{
    extern __shared__ char smem[];
    const uint32_t sbu = smem_u32(smem);
    float* xs    = (float*)(smem + X_OFF);
    float* e_arr = (float*)(smem + E_OFF);
    int*   sbat  = (int*)  (smem + BT_OFF);
    float* sb1   = (float*)(smem + SB1_OFF);
    float* sw2   = (float*)(smem + SW2_OFF);

    const int tid = threadIdx.x;
    const int wid = tid >> 5;
    const int lid = tid & 31;
    const long long row0 = (long long)blockIdx.x * TILE;
    const int nrows = (N - row0 < TILE) ? (int)(N - row0) : TILE;

    // ---- stage x via cp.async (x read from DRAM exactly once) -------------
    {
        const float4* gx = (const float4*)x + row0 * 16;
        const int nload = nrows * 16;
        for (int i = tid; i < nload; i += NT)
            cp_async16(sbu + X_OFF + (i >> 4) * (XPITCH * 4) + (i & 15) * 16,
                       gx + i);
    }

    // ---- W -> bf16 hi/lo in SMEM, coalesced k-pair form (overlaps cp.async)
    for (int p = tid; p < 1024; p += NT) {
        int n = p & 31, kp = p >> 5;           // k-pair kp -> k = 2kp, 2kp+1
        float v0 = Wg1[(2 * kp) * 32 + n];
        float v1 = Wg1[(2 * kp + 1) * 32 + n];
        uint32_t h = bf16x2_pack(v1, v0);
        uint32_t lo = bf16x2_pack(v1 - __uint_as_float(h & 0xffff0000u),
                                  v0 - __uint_as_float(h << 16));
        *(uint32_t*)(smem + WH_OFF + n * 144 + kp * 4) = h;
        *(uint32_t*)(smem + WL_OFF + n * 144 + kp * 4) = lo;
    }

    // ---- batch ids + biases ----------------------------------------------
    {
        const int*       b32 = (const int*)batch;
        const long long* b64 = (const long long*)batch;
        bool is64 = (b32[N - 1] == 0);
        for (int i = tid; i < TILE; i += NT)
            sbat[i] = (i < nrows)
                    ? (is64 ? (int)b64[row0 + i] : b32[row0 + i]) : -1;
        if (tid < 32) { sb1[tid] = bg1[tid]; sw2[tid] = Wg2[tid]; }
        cp_async_wait_all();
    }
    __syncthreads();

    const float b2v = __ldg(&bg2[0]);

    // ======================================================================
    // Gate: warp w handles rows [16w, 16w+16). A-frags from fp32 SMEM,
    // converted to bf16 hi/lo in registers. 3-term mma (hi*hi+hi*lo+lo*hi).
    // ======================================================================
    {
        const int R0  = wid * 16;
        const int grp = lid >> 2;                 // row within chunk half
        const int tig = lid & 3;                  // k-pair selector
        const float* xr  = xs + (R0 + grp) * XPITCH + tig * 2;
        const float* xr8 = xr + 8 * XPITCH;

        float acc[4][4];
#pragma unroll
        for (int nt = 0; nt < 4; nt++)
#pragma unroll
            for (int j = 0; j < 4; j++) acc[nt][j] = 0.f;

#pragma unroll
        for (int kk = 0; kk < 4; kk++) {
            const int kb = kk * 16;
            float2 p00 = *(const float2*)(xr  + kb);       // a0: row g,   k lo
            float2 p01 = *(const float2*)(xr8 + kb);       // a1: row g+8, k lo
            float2 p10 = *(const float2*)(xr  + kb + 8);   // a2: row g,   k hi
            float2 p11 = *(const float2*)(xr8 + kb + 8);   // a3: row g+8, k hi
            uint32_t ah0 = bf16x2_pack(p00.y, p00.x);
            uint32_t ah1 = bf16x2_pack(p01.y, p01.x);
            uint32_t ah2 = bf16x2_pack(p10.y, p10.x);
            uint32_t ah3 = bf16x2_pack(p11.y, p11.x);
            uint32_t al0 = bf16x2_pack(p00.y - __uint_as_float(ah0 & 0xffff0000u),
                                       p00.x - __uint_as_float(ah0 << 16));
            uint32_t al1 = bf16x2_pack(p01.y - __uint_as_float(ah1 & 0xffff0000u),
                                       p01.x - __uint_as_float(ah1 << 16));
            uint32_t al2 = bf16x2_pack(p10.y - __uint_as_float(ah2 & 0xffff0000u),
                                       p10.x - __uint_as_float(ah2 << 16));
            uint32_t al3 = bf16x2_pack(p11.y - __uint_as_float(ah3 & 0xffff0000u),
                                       p11.x - __uint_as_float(ah3 << 16));
#pragma unroll
            for (int nt = 0; nt < 4; nt++) {
                // B-frag: lane -> n = nt*8 + grp, k = tig*2 (+8 for b1)
                const char* wrh = smem + WH_OFF + (nt * 8 + grp) * 144 + kb * 2 + tig * 4;
                const char* wrl = smem + WL_OFF + (nt * 8 + grp) * 144 + kb * 2 + tig * 4;
                uint32_t bh0 = *(const uint32_t*)wrh;
                uint32_t bh1 = *(const uint32_t*)(wrh + 16);
                uint32_t bl0 = *(const uint32_t*)wrl;
                uint32_t bl1 = *(const uint32_t*)(wrl + 16);
                mma_bf16(acc[nt], ah0, ah1, ah2, ah3, bh0, bh1);  // hi*hi
                mma_bf16(acc[nt], ah0, ah1, ah2, ah3, bl0, bl1);  // hi*lo
                mma_bf16(acc[nt], al0, al1, al2, al3, bh0, bh1);  // lo*hi
            }
        }

        // Epilogue: g = relu(h+bg1).Wg2 + bg2 -> e = exp(g); rows g, g+8.
        float pr = 0.f, pr8 = 0.f;
#pragma unroll
        for (int nt = 0; nt < 4; nt++) {
            int c0 = nt * 8 + 2 * tig;
            float b10 = sb1[c0], b11 = sb1[c0 + 1];
            float w20 = sw2[c0], w21 = sw2[c0 + 1];
            pr  += fmaxf(acc[nt][0] + b10, 0.f) * w20
                 + fmaxf(acc[nt][1] + b11, 0.f) * w21;
            pr8 += fmaxf(acc[nt][2] + b10, 0.f) * w20
                 + fmaxf(acc[nt][3] + b11, 0.f) * w21;
        }
#pragma unroll
        for (int o = 1; o <= 2; o <<= 1) {
            pr  += __shfl_xor_sync(0xffffffffu, pr,  o);
            pr8 += __shfl_xor_sync(0xffffffffu, pr8, o);
        }
        if (tig == 0) {
            e_arr[R0 + grp]     = __expf(fminf(pr  + b2v, 80.f));
            e_arr[R0 + grp + 8] = __expf(fminf(pr8 + b2v, 80.f));
        }
    }
    __syncthreads();

    // ======================================================================
    // Segmented accumulation: 8 strips x 16 rows; thread = float2 col pair.
    // Fast path when the strip has no segment boundary (common case).
    // ======================================================================
    {
        const int st = tid >> 5;           // strip 0..7
        const int l  = tid & 31;
        const int rb = st * 16;
        const int c2 = l * 2;
        const int first = sbat[rb], last = sbat[rb + 15];

        if (first == last) {
            if (first >= 0) {
                float a0 = 0.f, a1 = 0.f, eacc = 0.f;
#pragma unroll
                for (int i = 0; i < 16; i++) {
                    float e  = e_arr[rb + i];
                    float2 v = *(const float2*)(xs + (rb + i) * XPITCH + c2);
                    a0 += e * v.x; a1 += e * v.y; eacc += e;
                }
                atomicAdd(&g_num[(long long)first * 64 + c2],     a0);
                atomicAdd(&g_num[(long long)first * 64 + c2 + 1], a1);
                if (l == 0) atomicAdd(&g_den[first], eacc);
            }
        } else {
            float a0 = 0.f, a1 = 0.f, eacc = 0.f;
            int cur = first;
            for (int i = 0; i < 16; i++) {
                int r  = rb + i;
                int sg = sbat[r];
                if (sg != cur) {
                    if (cur >= 0) {
                        atomicAdd(&g_num[(long long)cur * 64 + c2],     a0);
                        atomicAdd(&g_num[(long long)cur * 64 + c2 + 1], a1);
                        if (l == 0) atomicAdd(&g_den[cur], eacc);
                    }
                    a0 = a1 = eacc = 0.f; cur = sg;
                }
                float e  = e_arr[r];
                float2 v = *(const float2*)(xs + r * XPITCH + c2);
                a0 += e * v.x; a1 += e * v.y; eacc += e;
            }
            if (cur >= 0) {
                atomicAdd(&g_num[(long long)cur * 64 + c2],     a0);
                atomicAdd(&g_num[(long long)cur * 64 + c2 + 1], a1);
                if (l == 0) atomicAdd(&g_den[cur], eacc);
            }
        }
    }
}

// ---------------------------------------------------------------------------
// Kernel 2: head MLP (+ self-clean accumulators for the next call/replay).
// 128 blocks x 256 thr; each warp processes 4 segments serially; hg values
// broadcast lane->warp via shfl (no shared staging inside the loop).
// ---------------------------------------------------------------------------
__global__ void __launch_bounds__(256) shothead_head(
    const float* __restrict__ Wm1, const float* __restrict__ bm1,
    const float* __restrict__ Wm2, const float* __restrict__ bm2,
    float* __restrict__ out, int B)
{
    __shared__ float sW[2048];
    const int tid = threadIdx.x;
    const int wid = tid >> 5;
    const int lid = tid & 31;

    for (int i = tid; i < 2048; i += 256) sW[i] = Wm1[i];

    const float b1v = __ldg(&bm1[lid]);
    const float w2v = __ldg(&Wm2[lid]);
    const float b2v = __ldg(&bm2[0]);
    __syncthreads();

    const int seg0 = blockIdx.x * 32 + wid * 4;
#pragma unroll
    for (int j = 0; j < 4; j++) {
        const int seg = seg0 + j;
        if (seg >= B) break;

        float d = g_den[seg];
        if (d == 0.f) d = 1.f;
        const float inv = 1.f / d;
        float h0 = g_num[(long long)seg * 64 + lid]      * inv;   // hg[lid]
        float h1 = g_num[(long long)seg * 64 + lid + 32] * inv;   // hg[lid+32]

        // self-clean: zero accumulators for the next launch/replay
        g_num[(long long)seg * 64 + lid]      = 0.f;
        g_num[(long long)seg * 64 + lid + 32] = 0.f;
        if (lid == 0) g_den[seg] = 0.f;

        // hm[lid] = sum_k hg[k] * Wm1[k][lid], hg[k] via register broadcast
        float hm = 0.f;
#pragma unroll
        for (int k = 0; k < 32; k++) {
            float hk = __shfl_sync(0xffffffffu, h0, k);
            hm = fmaf(hk, sW[k * 32 + lid], hm);
        }
#pragma unroll
        for (int k = 0; k < 32; k++) {
            float hk = __shfl_sync(0xffffffffu, h1, k);
            hm = fmaf(hk, sW[(k + 32) * 32 + lid], hm);
        }

        float c = fmaxf(hm + b1v, 0.f) * w2v;
#pragma unroll
        for (int o = 16; o; o >>= 1) c += __shfl_xor_sync(0xffffffffu, c, o);
        if (lid == 0) out[seg] = c + b2v;
    }
}

// ---------------------------------------------------------------------------
// Host launch (graph-capturable: 2 kernel launches)
// ---------------------------------------------------------------------------
extern "C" void kernel_launch(void* const* d_in, const int* in_sizes, int n_in,
                              void* d_out, int out_size)
{
    const float* x   = (const float*)d_in[0];
    const void*  bat = d_in[1];
    const float* Wg1 = (const float*)d_in[2];
    const float* bg1 = (const float*)d_in[3];
    const float* Wg2 = (const float*)d_in[4];
    const float* bg2 = (const float*)d_in[5];
    const float* Wm1 = (const float*)d_in[6];
    const float* bm1 = (const float*)d_in[7];
    const float* Wm2 = (const float*)d_in[8];
    const float* bm2 = (const float*)d_in[9];

    const int N = in_sizes[1];     // rows
    const int B = out_size;        // segments

    const int nchunks = (N + TILE - 1) / TILE;
    shothead_chunk<<<nchunks, NT, SMEM_BYTES>>>(x, bat, Wg1, bg1, Wg2, bg2, N, B);

    shothead_head<<<(B + 31) / 32, 256>>>(Wm1, bm1, Wm2, bm2, (float*)d_out, B);
}

// round 13
// speedup vs baseline: 1.0562x; 1.0562x over previous
#include <cuda_runtime.h>
#include <cuda_bf16.h>
#include <cstdint>

// ============================================================================
// ShotHead (GB300 / sm_100a) — round 13: head = max-parallel short-chain.
//   gate  = relu(x @ Wg1 + bg1) @ Wg2 + bg2
//   alpha = e^g / seg_sum(e^g)          (shift-invariant softmax, single pass)
//   hg    = segment_sum(alpha * x)
//   out   = relu(hg @ Wm1 + bm1) @ Wm2 + bm2
//
// Round-12 lesson: 128-block/4-seg-per-warp head REGRESSED (18.3us, occ 11%).
// Tiny-work kernels here want MAX warps + SHORT chains. This head: 512 blocks,
// warp per segment, Wm1 staged TRANSPOSED (pad-68) so the dot is 16 x
// (2 LDS.128 + 4 FMA) with 4 independent accumulators (chain 64cyc, was 256).
// Chunk kernel identical to the 80.9us round-10 version.
// ============================================================================

#define TILE     128
#define NT       256
#define XPITCH   68          // floats per x row in SMEM (17 float4, pad)
#define MAXB     8192

__device__ float g_num[MAXB * 64];
__device__ float g_den[MAXB];

// ---------------- helpers ---------------------------------------------------
__device__ __forceinline__ uint32_t smem_u32(const void* p) {
    uint32_t a;
    asm("{ .reg .u64 t; cvta.to.shared.u64 t, %1; cvt.u32.u64 %0, t; }"
        : "=r"(a) : "l"(p));
    return a;
}
__device__ __forceinline__ void cp_async16(uint32_t dst, const void* src) {
    asm volatile("cp.async.cg.shared.global [%0], [%1], 16;"
                 :: "r"(dst), "l"(src) : "memory");
}
__device__ __forceinline__ void cp_async_wait_all() {
    asm volatile("cp.async.commit_group;\n\tcp.async.wait_group 0;" ::: "memory");
}
__device__ __forceinline__ uint32_t bf16x2_pack(float hi_elem, float lo_elem) {
    uint32_t r;   // low 16 = lo_elem, high 16 = hi_elem
    asm("cvt.rn.bf16x2.f32 %0, %1, %2;" : "=r"(r) : "f"(hi_elem), "f"(lo_elem));
    return r;
}
__device__ __forceinline__ void mma_bf16(float* c, uint32_t a0, uint32_t a1,
                                         uint32_t a2, uint32_t a3,
                                         uint32_t b0, uint32_t b1) {
    asm volatile(
        "mma.sync.aligned.m16n8k16.row.col.f32.bf16.bf16.f32 "
        "{%0,%1,%2,%3}, {%4,%5,%6,%7}, {%8,%9}, {%0,%1,%2,%3};"
        : "+f"(c[0]), "+f"(c[1]), "+f"(c[2]), "+f"(c[3])
        : "r"(a0), "r"(a1), "r"(a2), "r"(a3), "r"(b0), "r"(b1));
}

// ---------------------------------------------------------------------------
// SMEM layout (bytes). W pitch = 72 bf16 = 144 B.
// ---------------------------------------------------------------------------
#define X_OFF    0                          /* 128 x 272B fp32               */
#define WH_OFF   34816                      /* Whi[n][k] 32 x 144B           */
#define WL_OFF   39424                      /* Wlo[n][k] 32 x 144B           */
#define E_OFF    44032                      /* float[128] e                  */
#define BT_OFF   44544                      /* int[128] segment ids          */
#define SB1_OFF  45056                      /* float[32] bg1                 */
#define SW2_OFF  45184                      /* float[32] Wg2                 */
#define SMEM_BYTES 45312

// ---------------------------------------------------------------------------
// Kernel 1: per-chunk gate + e + segmented partial sums. Grid = ceil(N/128).
// (identical to the validated 80.9us version)
// ---------------------------------------------------------------------------
__global__ void __launch_bounds__(NT, 4) shothead_chunk(
    const float* __restrict__ x, const void* __restrict__ batch,
    const float* __restrict__ Wg1, const float* __restrict__ bg1,
    const float* __restrict__ Wg2, const float* __restrict__ bg2,
    int N, int B)
{
    extern __shared__ char smem[];
    const uint32_t sbu = smem_u32(smem);
    float* xs    = (float*)(smem + X_OFF);
    float* e_arr = (float*)(smem + E_OFF);
    int*   sbat  = (int*)  (smem + BT_OFF);
    float* sb1   = (float*)(smem + SB1_OFF);
    float* sw2   = (float*)(smem + SW2_OFF);

    const int tid = threadIdx.x;
    const int wid = tid >> 5;
    const int lid = tid & 31;
    const long long row0 = (long long)blockIdx.x * TILE;
    const int nrows = (N - row0 < TILE) ? (int)(N - row0) : TILE;

    // ---- stage x via cp.async (x read from DRAM exactly once) -------------
    {
        const float4* gx = (const float4*)x + row0 * 16;
        const int nload = nrows * 16;
        for (int i = tid; i < nload; i += NT)
            cp_async16(sbu + X_OFF + (i >> 4) * (XPITCH * 4) + (i & 15) * 16,
                       gx + i);
    }

    // ---- W -> bf16 hi/lo in SMEM, coalesced k-pair form (overlaps cp.async)
    for (int p = tid; p < 1024; p += NT) {
        int n = p & 31, kp = p >> 5;           // k-pair kp -> k = 2kp, 2kp+1
        float v0 = Wg1[(2 * kp) * 32 + n];
        float v1 = Wg1[(2 * kp + 1) * 32 + n];
        uint32_t h = bf16x2_pack(v1, v0);
        uint32_t lo = bf16x2_pack(v1 - __uint_as_float(h & 0xffff0000u),
                                  v0 - __uint_as_float(h << 16));
        *(uint32_t*)(smem + WH_OFF + n * 144 + kp * 4) = h;
        *(uint32_t*)(smem + WL_OFF + n * 144 + kp * 4) = lo;
    }

    // ---- batch ids + biases ----------------------------------------------
    {
        const int*       b32 = (const int*)batch;
        const long long* b64 = (const long long*)batch;
        bool is64 = (b32[N - 1] == 0);
        for (int i = tid; i < TILE; i += NT)
            sbat[i] = (i < nrows)
                    ? (is64 ? (int)b64[row0 + i] : b32[row0 + i]) : -1;
        if (tid < 32) { sb1[tid] = bg1[tid]; sw2[tid] = Wg2[tid]; }
        cp_async_wait_all();
    }
    __syncthreads();

    const float b2v = __ldg(&bg2[0]);

    // ======================================================================
    // Gate: warp w handles rows [16w, 16w+16). A-frags from fp32 SMEM,
    // converted to bf16 hi/lo in registers. 3-term mma (hi*hi+hi*lo+lo*hi).
    // ======================================================================
    {
        const int R0  = wid * 16;
        const int grp = lid >> 2;                 // row within chunk half
        const int tig = lid & 3;                  // k-pair selector
        const float* xr  = xs + (R0 + grp) * XPITCH + tig * 2;
        const float* xr8 = xr + 8 * XPITCH;

        float acc[4][4];
#pragma unroll
        for (int nt = 0; nt < 4; nt++)
#pragma unroll
            for (int j = 0; j < 4; j++) acc[nt][j] = 0.f;

#pragma unroll
        for (int kk = 0; kk < 4; kk++) {
            const int kb = kk * 16;
            float2 p00 = *(const float2*)(xr  + kb);       // a0: row g,   k lo
            float2 p01 = *(const float2*)(xr8 + kb);       // a1: row g+8, k lo
            float2 p10 = *(const float2*)(xr  + kb + 8);   // a2: row g,   k hi
            float2 p11 = *(const float2*)(xr8 + kb + 8);   // a3: row g+8, k hi
            uint32_t ah0 = bf16x2_pack(p00.y, p00.x);
            uint32_t ah1 = bf16x2_pack(p01.y, p01.x);
            uint32_t ah2 = bf16x2_pack(p10.y, p10.x);
            uint32_t ah3 = bf16x2_pack(p11.y, p11.x);
            uint32_t al0 = bf16x2_pack(p00.y - __uint_as_float(ah0 & 0xffff0000u),
                                       p00.x - __uint_as_float(ah0 << 16));
            uint32_t al1 = bf16x2_pack(p01.y - __uint_as_float(ah1 & 0xffff0000u),
                                       p01.x - __uint_as_float(ah1 << 16));
            uint32_t al2 = bf16x2_pack(p10.y - __uint_as_float(ah2 & 0xffff0000u),
                                       p10.x - __uint_as_float(ah2 << 16));
            uint32_t al3 = bf16x2_pack(p11.y - __uint_as_float(ah3 & 0xffff0000u),
                                       p11.x - __uint_as_float(ah3 << 16));
#pragma unroll
            for (int nt = 0; nt < 4; nt++) {
                // B-frag: lane -> n = nt*8 + grp, k = tig*2 (+8 for b1)
                const char* wrh = smem + WH_OFF + (nt * 8 + grp) * 144 + kb * 2 + tig * 4;
                const char* wrl = smem + WL_OFF + (nt * 8 + grp) * 144 + kb * 2 + tig * 4;
                uint32_t bh0 = *(const uint32_t*)wrh;
                uint32_t bh1 = *(const uint32_t*)(wrh + 16);
                uint32_t bl0 = *(const uint32_t*)wrl;
                uint32_t bl1 = *(const uint32_t*)(wrl + 16);
                mma_bf16(acc[nt], ah0, ah1, ah2, ah3, bh0, bh1);  // hi*hi
                mma_bf16(acc[nt], ah0, ah1, ah2, ah3, bl0, bl1);  // hi*lo
                mma_bf16(acc[nt], al0, al1, al2, al3, bh0, bh1);  // lo*hi
            }
        }

        // Epilogue: g = relu(h+bg1).Wg2 + bg2 -> e = exp(g); rows g, g+8.
        float pr = 0.f, pr8 = 0.f;
#pragma unroll
        for (int nt = 0; nt < 4; nt++) {
            int c0 = nt * 8 + 2 * tig;
            float b10 = sb1[c0], b11 = sb1[c0 + 1];
            float w20 = sw2[c0], w21 = sw2[c0 + 1];
            pr  += fmaxf(acc[nt][0] + b10, 0.f) * w20
                 + fmaxf(acc[nt][1] + b11, 0.f) * w21;
            pr8 += fmaxf(acc[nt][2] + b10, 0.f) * w20
                 + fmaxf(acc[nt][3] + b11, 0.f) * w21;
        }
#pragma unroll
        for (int o = 1; o <= 2; o <<= 1) {
            pr  += __shfl_xor_sync(0xffffffffu, pr,  o);
            pr8 += __shfl_xor_sync(0xffffffffu, pr8, o);
        }
        if (tig == 0) {
            e_arr[R0 + grp]     = __expf(fminf(pr  + b2v, 80.f));
            e_arr[R0 + grp + 8] = __expf(fminf(pr8 + b2v, 80.f));
        }
    }
    __syncthreads();

    // ======================================================================
    // Segmented accumulation: 8 strips x 16 rows; thread = float2 col pair.
    // Fast path when the strip has no segment boundary (common case).
    // ======================================================================
    {
        const int st = tid >> 5;           // strip 0..7
        const int l  = tid & 31;
        const int rb = st * 16;
        const int c2 = l * 2;
        const int first = sbat[rb], last = sbat[rb + 15];

        if (first == last) {
            if (first >= 0) {
                float a0 = 0.f, a1 = 0.f, eacc = 0.f;
#pragma unroll
                for (int i = 0; i < 16; i++) {
                    float e  = e_arr[rb + i];
                    float2 v = *(const float2*)(xs + (rb + i) * XPITCH + c2);
                    a0 += e * v.x; a1 += e * v.y; eacc += e;
                }
                atomicAdd(&g_num[(long long)first * 64 + c2],     a0);
                atomicAdd(&g_num[(long long)first * 64 + c2 + 1], a1);
                if (l == 0) atomicAdd(&g_den[first], eacc);
            }
        } else {
            float a0 = 0.f, a1 = 0.f, eacc = 0.f;
            int cur = first;
            for (int i = 0; i < 16; i++) {
                int r  = rb + i;
                int sg = sbat[r];
                if (sg != cur) {
                    if (cur >= 0) {
                        atomicAdd(&g_num[(long long)cur * 64 + c2],     a0);
                        atomicAdd(&g_num[(long long)cur * 64 + c2 + 1], a1);
                        if (l == 0) atomicAdd(&g_den[cur], eacc);
                    }
                    a0 = a1 = eacc = 0.f; cur = sg;
                }
                float e  = e_arr[r];
                float2 v = *(const float2*)(xs + r * XPITCH + c2);
                a0 += e * v.x; a1 += e * v.y; eacc += e;
            }
            if (cur >= 0) {
                atomicAdd(&g_num[(long long)cur * 64 + c2],     a0);
                atomicAdd(&g_num[(long long)cur * 64 + c2 + 1], a1);
                if (l == 0) atomicAdd(&g_den[cur], eacc);
            }
        }
    }
}

// ---------------------------------------------------------------------------
// Kernel 2: head MLP (+ self-clean accumulators for next call/replay).
// 512 blocks x 256 thr, warp per segment. Wm1 staged TRANSPOSED sWt[h][k]
// (pitch 68 -> conflict-free STS, 16B-aligned lane-contiguous LDS.128).
// Dot: 16 x (2 LDS.128 + 4 FMA), 4 independent accumulators.
// ---------------------------------------------------------------------------
#define WT_PITCH 68
__global__ void __launch_bounds__(256) shothead_head(
    const float* __restrict__ Wm1, const float* __restrict__ bm1,
    const float* __restrict__ Wm2, const float* __restrict__ bm2,
    float* __restrict__ out, int B)
{
    __shared__ float sWt[32 * WT_PITCH];     // sWt[h*68 + k] = Wm1[k][h]
    __shared__ float shg[8][64];
    const int tid = threadIdx.x;
    const int wid = tid >> 5;
    const int lid = tid & 31;

    // Transposed staging: consecutive tid -> consecutive h -> stride-68 STS
    // (68 mod 32 = 4 -> distinct banks across the warp).
    for (int i = tid; i < 2048; i += 256) {
        int h = i & 31, k = i >> 5;
        sWt[h * WT_PITCH + k] = Wm1[i];
    }

    // Independent per-warp work under the staging shadow.
    const int seg = blockIdx.x * 8 + wid;
    if (seg < B) {
        float d = g_den[seg];
        if (d == 0.f) d = 1.f;
        const float inv = 1.f / d;
        float n0 = g_num[(long long)seg * 64 + lid];
        float n1 = g_num[(long long)seg * 64 + lid + 32];
        shg[wid][lid]      = n0 * inv;
        shg[wid][lid + 32] = n1 * inv;
        // self-clean for the next launch/replay
        g_num[(long long)seg * 64 + lid]      = 0.f;
        g_num[(long long)seg * 64 + lid + 32] = 0.f;
        if (lid == 0) g_den[seg] = 0.f;
    }
    const float b1v = __ldg(&bm1[lid]);
    const float w2v = __ldg(&Wm2[lid]);
    const float b2v = __ldg(&bm2[0]);
    __syncthreads();

    if (seg < B) {
        const float* hgp = shg[wid];
        const float* wr  = sWt + lid * WT_PITCH;
        float a0 = 0.f, a1 = 0.f, a2 = 0.f, a3 = 0.f;
#pragma unroll
        for (int k4 = 0; k4 < 16; k4++) {
            float4 hg4 = *(const float4*)(hgp + k4 * 4);   // broadcast LDS.128
            float4 wv  = *(const float4*)(wr  + k4 * 4);   // lane-contig LDS.128
            a0 = fmaf(hg4.x, wv.x, a0);
            a1 = fmaf(hg4.y, wv.y, a1);
            a2 = fmaf(hg4.z, wv.z, a2);
            a3 = fmaf(hg4.w, wv.w, a3);
        }
        float hm = (a0 + a1) + (a2 + a3);
        float c = fmaxf(hm + b1v, 0.f) * w2v;
#pragma unroll
        for (int o = 16; o; o >>= 1) c += __shfl_xor_sync(0xffffffffu, c, o);
        if (lid == 0) out[seg] = c + b2v;
    }
}

// ---------------------------------------------------------------------------
// Host launch (graph-capturable: 2 kernel launches)
// ---------------------------------------------------------------------------
extern "C" void kernel_launch(void* const* d_in, const int* in_sizes, int n_in,
                              void* d_out, int out_size)
{
    const float* x   = (const float*)d_in[0];
    const void*  bat = d_in[1];
    const float* Wg1 = (const float*)d_in[2];
    const float* bg1 = (const float*)d_in[3];
    const float* Wg2 = (const float*)d_in[4];
    const float* bg2 = (const float*)d_in[5];
    const float* Wm1 = (const float*)d_in[6];
    const float* bm1 = (const float*)d_in[7];
    const float* Wm2 = (const float*)d_in[8];
    const float* bm2 = (const float*)d_in[9];

    const int N = in_sizes[1];     // rows
    const int B = out_size;        // segments

    const int nchunks = (N + TILE - 1) / TILE;
    shothead_chunk<<<nchunks, NT, SMEM_BYTES>>>(x, bat, Wg1, bg1, Wg2, bg2, N, B);

    shothead_head<<<(B + 7) / 8, 256>>>(Wm1, bm1, Wm2, bm2, (float*)d_out, B);
}